// round 4
// baseline (speedup 1.0000x reference)
#include <cuda_runtime.h>

// Problem constants (fixed by the reference setup_inputs)
#define B_NODES 16384
#define KNEIGH  32
#define HDIM    512
#define DOUT    256

// Pooled hidden activations (scratch): 2 x 16384 x 512 f32 = 64 MB static device mem
__device__ float g_feat_pooled[B_NODES * HDIM];
__device__ float g_geto_pooled[B_NODES * HDIM];

// ---- packed f32x2 helpers (Blackwell sm_100+: fma.rn.f32x2) ----
__device__ __forceinline__ unsigned long long pack2(float x, float y) {
    unsigned long long r;
    asm("mov.b64 %0, {%1, %2};" : "=l"(r) : "f"(x), "f"(y));
    return r;
}
__device__ __forceinline__ void fma2(unsigned long long& d,
                                     unsigned long long a,
                                     unsigned long long b) {
    asm("fma.rn.f32x2 %0, %1, %2, %0;" : "+l"(d) : "l"(a), "l"(b));
}
__device__ __forceinline__ float2 unpack2(unsigned long long v) {
    float x, y;
    asm("mov.b64 {%0, %1}, %2;" : "=f"(x), "=f"(y) : "l"(v));
    return make_float2(x, y);
}

// =====================================================================
// Kernel 1: fused per-neighbor MLP + ReLU + mean-pool
//   X      : [B*K, D]  (row-major, rows = b*K + k)
//   W      : [D, 512]
//   bias   : [512]
//   writes : pooled[b][h] = (1/K) * sum_k relu(X[b,k,:] @ W[:,h] + bias[h])
// Block: 256 threads, tile = 128 rows (4 batches x 32 neighbors) x 128 cols.
// Per-thread 8x8 register tile held as 8x4 f32x2 accumulators.
// =====================================================================
template <int D, int WHICH>
__global__ void __launch_bounds__(256, 2)
pool_mlp_kernel(const float* __restrict__ X,
                const float* __restrict__ W,
                const float* __restrict__ bias)
{
    __shared__ float As[128][33];                 // padded: conflict-free a-broadcast
    __shared__ __align__(16) float Ws[32][128];   // chunk of W, col-tile
    __shared__ float bs[128];
    __shared__ float ps[4][128];                  // per-batch pooled partials

    const int tid = threadIdx.x;
    const int tx  = tid & 15;      // col group  (8 cols each)
    const int ty  = tid >> 4;      // row group  (8 rows each)
    const int colbase = blockIdx.x * 128;
    const int rowbase = blockIdx.y * 128;

    if (tid < 128) bs[tid] = bias[colbase + tid];
    ((float*)ps)[tid]       = 0.0f;
    ((float*)ps)[tid + 256] = 0.0f;

    unsigned long long acc[8][4];
#pragma unroll
    for (int i = 0; i < 8; i++)
#pragma unroll
        for (int p = 0; p < 4; p++) acc[i][p] = 0ull;

#pragma unroll
    for (int c0 = 0; c0 < D; c0 += 32) {
        __syncthreads();
        // stage A chunk: 128 rows x 32 depth (rows contiguous in gmem)
        // 128*32 floats = 1024 float4: row = idx/8, col-group = idx%8
#pragma unroll
        for (int it = 0; it < 4; it++) {
            int idx = tid + it * 256;
            int row = idx >> 3;
            int j   = (idx & 7) * 4;
            float4 v = *(const float4*)(X + (rowbase + row) * D + c0 + j);
            As[row][j]     = v.x;
            As[row][j + 1] = v.y;
            As[row][j + 2] = v.z;
            As[row][j + 3] = v.w;
        }
        // stage W chunk: 32 depth x 128 cols
        // 32*128 floats = 1024 float4: depth = idx/32, col-group = idx%32
#pragma unroll
        for (int it = 0; it < 4; it++) {
            int idx = tid + it * 256;
            int d = idx >> 5;           // 0..31
            int j = (idx & 31) * 4;     // 0..124
            *(float4*)&Ws[d][j] = *(const float4*)(W + (c0 + d) * HDIM + colbase + j);
        }
        __syncthreads();

#pragma unroll 8
        for (int dj = 0; dj < 32; dj++) {
            unsigned long long a2[8];
#pragma unroll
            for (int i = 0; i < 8; i++) {
                float a = As[ty * 8 + i][dj];
                a2[i] = pack2(a, a);
            }
            longlong2 w01 = *(const longlong2*)&Ws[dj][tx * 8];
            longlong2 w23 = *(const longlong2*)&Ws[dj][tx * 8 + 4];
            unsigned long long b0 = (unsigned long long)w01.x;
            unsigned long long b1 = (unsigned long long)w01.y;
            unsigned long long b2 = (unsigned long long)w23.x;
            unsigned long long b3 = (unsigned long long)w23.y;
#pragma unroll
            for (int i = 0; i < 8; i++) {
                fma2(acc[i][0], a2[i], b0);
                fma2(acc[i][1], a2[i], b1);
                fma2(acc[i][2], a2[i], b2);
                fma2(acc[i][3], a2[i], b3);
            }
        }
    }

    // Epilogue: bias + relu, reduce this thread's 8 rows (all same batch since
    // 8 | 32), then smem-atomic pool across the 4 ty-groups sharing a batch.
    const int bl = ty >> 2;  // local batch index 0..3
#pragma unroll
    for (int p = 0; p < 4; p++) {
        const int c0i = tx * 8 + 2 * p;
        float bv0 = bs[c0i], bv1 = bs[c0i + 1];
        float s0 = 0.0f, s1 = 0.0f;
#pragma unroll
        for (int i = 0; i < 8; i++) {
            float2 v = unpack2(acc[i][p]);
            s0 += fmaxf(v.x + bv0, 0.0f);
            s1 += fmaxf(v.y + bv1, 0.0f);
        }
        atomicAdd(&ps[bl][c0i],     s0);
        atomicAdd(&ps[bl][c0i + 1], s1);
    }
    __syncthreads();

    float* pooled = WHICH ? g_geto_pooled : g_feat_pooled;
#pragma unroll
    for (int r = 0; r < 2; r++) {
        int idx = tid + r * 256;
        int b2  = idx >> 7;
        int c   = idx & 127;
        pooled[(blockIdx.y * 4 + b2) * HDIM + colbase + c] =
            ps[b2][c] * (1.0f / (float)KNEIGH);
    }
}

// =====================================================================
// Kernel 2: out = relu( Aself[B,DSELF] @ Wself[DSELF,256]
//                      + pooled[B,512] @ Wneigh[512,256] )
// Same 128x128 tiling; the depth loop walks [self | pooled] as one
// virtual 640/576-deep GEMM.
// =====================================================================
template <int DSELF, int WHICH>
__global__ void __launch_bounds__(256, 2)
combine_kernel(const float* __restrict__ Aself,
               const float* __restrict__ Wself,
               const float* __restrict__ Wneigh,
               float* __restrict__ out)
{
    __shared__ float As[128][33];
    __shared__ __align__(16) float Ws[32][128];

    const int tid = threadIdx.x;
    const int tx  = tid & 15;
    const int ty  = tid >> 4;
    const int colbase = blockIdx.x * 128;
    const int rowbase = blockIdx.y * 128;
    const float* pooled = WHICH ? g_geto_pooled : g_feat_pooled;

    unsigned long long acc[8][4];
#pragma unroll
    for (int i = 0; i < 8; i++)
#pragma unroll
        for (int p = 0; p < 4; p++) acc[i][p] = 0ull;

    const int NC1 = DSELF / 32;
    for (int ch = 0; ch < NC1 + HDIM / 32; ch++) {
        const float* A;
        const float* Wp;
        int lda, c0;
        if (ch < NC1) { A = Aself;  Wp = Wself;  lda = DSELF; c0 = ch * 32; }
        else          { A = pooled; Wp = Wneigh; lda = HDIM;  c0 = (ch - NC1) * 32; }

        __syncthreads();
#pragma unroll
        for (int it = 0; it < 4; it++) {
            int idx = tid + it * 256;
            int row = idx >> 3;
            int j   = (idx & 7) * 4;
            float4 v = *(const float4*)(A + (rowbase + row) * lda + c0 + j);
            As[row][j]     = v.x;
            As[row][j + 1] = v.y;
            As[row][j + 2] = v.z;
            As[row][j + 3] = v.w;
        }
        // W chunk: 32 x 128, depth = idx/32, col-group = idx%32
#pragma unroll
        for (int it = 0; it < 4; it++) {
            int idx = tid + it * 256;
            int d = idx >> 5;           // 0..31
            int j = (idx & 31) * 4;     // 0..124
            *(float4*)&Ws[d][j] = *(const float4*)(Wp + (c0 + d) * DOUT + colbase + j);
        }
        __syncthreads();

#pragma unroll 8
        for (int dj = 0; dj < 32; dj++) {
            unsigned long long a2[8];
#pragma unroll
            for (int i = 0; i < 8; i++) {
                float a = As[ty * 8 + i][dj];
                a2[i] = pack2(a, a);
            }
            longlong2 w01 = *(const longlong2*)&Ws[dj][tx * 8];
            longlong2 w23 = *(const longlong2*)&Ws[dj][tx * 8 + 4];
            unsigned long long b0 = (unsigned long long)w01.x;
            unsigned long long b1 = (unsigned long long)w01.y;
            unsigned long long b2 = (unsigned long long)w23.x;
            unsigned long long b3 = (unsigned long long)w23.y;
#pragma unroll
            for (int i = 0; i < 8; i++) {
                fma2(acc[i][0], a2[i], b0);
                fma2(acc[i][1], a2[i], b1);
                fma2(acc[i][2], a2[i], b2);
                fma2(acc[i][3], a2[i], b3);
            }
        }
    }

    // relu + store
#pragma unroll
    for (int i = 0; i < 8; i++) {
        int row = rowbase + ty * 8 + i;
#pragma unroll
        for (int p = 0; p < 4; p++) {
            float2 v = unpack2(acc[i][p]);
            v.x = fmaxf(v.x, 0.0f);
            v.y = fmaxf(v.y, 0.0f);
            *(float2*)(out + row * DOUT + colbase + tx * 8 + 2 * p) = v;
        }
    }
}

// =====================================================================
// Launch. Input order per metadata:
//  0 self_vecs[B,128] 1 neigh_vecs[B,K,128] 2 self_geto[B,64] 3 neigh_geto[B,K,64]
//  4 W_feat_mlp[128,512] 5 b_feat_mlp[512] 6 W_geto_mlp[64,512] 7 b_geto_mlp[512]
//  8 neigh_feat_weights[512,256] 9 self_feat_weights[128,256]
// 10 self_geto_weights[64,256]  11 neigh_geto_weights[512,256]
// Output: node_output[B,256] then geto_output[B,256] (tuple flattened in order).
// =====================================================================
extern "C" void kernel_launch(void* const* d_in, const int* in_sizes, int n_in,
                              void* d_out, int out_size)
{
    const float* self_vecs  = (const float*)d_in[0];
    const float* neigh_vecs = (const float*)d_in[1];
    const float* self_geto  = (const float*)d_in[2];
    const float* neigh_geto = (const float*)d_in[3];
    const float* W_feat     = (const float*)d_in[4];
    const float* b_feat     = (const float*)d_in[5];
    const float* W_geto     = (const float*)d_in[6];
    const float* b_geto     = (const float*)d_in[7];
    const float* W_nf       = (const float*)d_in[8];
    const float* W_sf       = (const float*)d_in[9];
    const float* W_sg       = (const float*)d_in[10];
    const float* W_ng       = (const float*)d_in[11];
    float* out = (float*)d_out;

    dim3 blk(256);
    dim3 grid_pool(HDIM / 128, (B_NODES * KNEIGH) / 128);   // (4, 4096)
    pool_mlp_kernel<128, 0><<<grid_pool, blk>>>(neigh_vecs, W_feat, b_feat);
    pool_mlp_kernel< 64, 1><<<grid_pool, blk>>>(neigh_geto, W_geto, b_geto);

    dim3 grid_comb(DOUT / 128, B_NODES / 128);               // (2, 128)
    combine_kernel<128, 0><<<grid_comb, blk>>>(self_vecs, W_sf, W_nf, out);
    combine_kernel< 64, 1><<<grid_comb, blk>>>(self_geto, W_sg, W_ng,
                                               out + B_NODES * DOUT);
}

// round 6
// speedup vs baseline: 2.2774x; 2.2774x over previous
#include <cuda_runtime.h>
#include <cuda_bf16.h>
#include <cstdint>

// Problem constants (fixed by the reference setup_inputs)
#define B_NODES 16384
#define KNEIGH  32
#define HDIM    512
#define DOUT    256

// Pooled hidden activations (scratch): 2 x 16384 x 512 f32 = 64 MB static device mem
__device__ float g_feat_pooled[B_NODES * HDIM];
__device__ float g_geto_pooled[B_NODES * HDIM];

// =====================================================================
// Helpers
// =====================================================================
__device__ __forceinline__ uint32_t smem_u32(const void* p) {
    uint32_t a;
    asm("{ .reg .u64 t; cvta.to.shared.u64 t, %1; cvt.u32.u64 %0, t; }"
        : "=r"(a) : "l"(p));
    return a;
}

__device__ __forceinline__ void ldsm_x4(uint32_t r[4], uint32_t addr) {
    asm volatile("ldmatrix.sync.aligned.m8n8.x4.shared.b16 {%0,%1,%2,%3}, [%4];"
        : "=r"(r[0]), "=r"(r[1]), "=r"(r[2]), "=r"(r[3]) : "r"(addr));
}
__device__ __forceinline__ void ldsm_x4_t(uint32_t r[4], uint32_t addr) {
    asm volatile("ldmatrix.sync.aligned.m8n8.x4.trans.shared.b16 {%0,%1,%2,%3}, [%4];"
        : "=r"(r[0]), "=r"(r[1]), "=r"(r[2]), "=r"(r[3]) : "r"(addr));
}
__device__ __forceinline__ void mma16816(float c[4], const uint32_t a[4],
                                         uint32_t b0, uint32_t b1) {
    asm volatile("mma.sync.aligned.m16n8k16.row.col.f32.bf16.bf16.f32 "
        "{%0,%1,%2,%3}, {%4,%5,%6,%7}, {%8,%9}, {%0,%1,%2,%3};"
        : "+f"(c[0]), "+f"(c[1]), "+f"(c[2]), "+f"(c[3])
        : "r"(a[0]), "r"(a[1]), "r"(a[2]), "r"(a[3]), "r"(b0), "r"(b1));
}

// split fp32x4 -> bf16 hi pair + lo (residual) pair
__device__ __forceinline__ void split4(float4 v, uint32_t& h0, uint32_t& h1,
                                       uint32_t& l0, uint32_t& l1) {
    __nv_bfloat16 hx = __float2bfloat16(v.x), hy = __float2bfloat16(v.y);
    __nv_bfloat16 hz = __float2bfloat16(v.z), hw = __float2bfloat16(v.w);
    __nv_bfloat162 H0; H0.x = hx; H0.y = hy;
    __nv_bfloat162 H1; H1.x = hz; H1.y = hw;
    h0 = *(uint32_t*)&H0; h1 = *(uint32_t*)&H1;
    __nv_bfloat162 L0, L1;
    L0.x = __float2bfloat16(v.x - __bfloat162float(hx));
    L0.y = __float2bfloat16(v.y - __bfloat162float(hy));
    L1.x = __float2bfloat16(v.z - __bfloat162float(hz));
    L1.y = __float2bfloat16(v.w - __bfloat162float(hw));
    l0 = *(uint32_t*)&L0; l1 = *(uint32_t*)&L1;
}

// ---- packed f32x2 helpers for the SIMT combine kernel ----
__device__ __forceinline__ unsigned long long pack2(float x, float y) {
    unsigned long long r;
    asm("mov.b64 %0, {%1, %2};" : "=l"(r) : "f"(x), "f"(y));
    return r;
}
__device__ __forceinline__ void fma2(unsigned long long& d,
                                     unsigned long long a,
                                     unsigned long long b) {
    asm("fma.rn.f32x2 %0, %1, %2, %0;" : "+l"(d) : "l"(a), "l"(b));
}
__device__ __forceinline__ float2 unpack2(unsigned long long v) {
    float x, y;
    asm("mov.b64 {%0, %1}, %2;" : "=f"(x), "=f"(y) : "l"(v));
    return make_float2(x, y);
}

// =====================================================================
// Kernel 1 (mma.sync bf16 3-split): fused per-neighbor MLP + ReLU + mean-pool
//   X[B*K, D] fp32 ; W[D, 512] ; bias[512]
//   pooled[b][h] = mean_k relu(X[b*32+k,:] @ W[:,h] + bias[h])
// CTA: 256 thr / 8 warps; tile 128 rows x 128 cols.
// warp (wrow,wcol): 32 rows (one batch) x 64 cols.
// W tile staged hi/lo once per CTA; A staged per tile in k=64 chunks.
// =====================================================================
template <int D, int WHICH>
__global__ void __launch_bounds__(256, 2)
pool_mma_kernel(const float* __restrict__ X,
                const float* __restrict__ W,
                const float* __restrict__ bias)
{
    constexpr int KC  = 64;                // k-chunk size
    constexpr int PA  = 144;               // A pitch bytes (64 bf16 + 16B pad)
    constexpr int PW  = 272;               // W pitch bytes (128 bf16 + 16B pad)
    constexpr int ASZ = 128 * PA;          // per-split A tile bytes
    constexpr int WSZ = D * PW;            // per-split W tile bytes
    constexpr int OFF_AHI = 512;
    constexpr int OFF_ALO = OFF_AHI + ASZ;
    constexpr int OFF_WHI = OFF_ALO + ASZ;

    extern __shared__ char smem[];
    float* bias_s = (float*)smem;
    const uint32_t sb = smem_u32(smem);
    const int tid  = threadIdx.x;
    const int lane = tid & 31;
    const int wid  = tid >> 5;
    const int wrow = wid & 3;              // 32-row group (batch within tile)
    const int wcol = wid >> 2;             // 64-col half
    const int colbase = blockIdx.x * 128;
    float* pooled = WHICH ? g_geto_pooled : g_feat_pooled;

    if (tid < 128) bias_s[tid] = bias[colbase + tid];

    // ---- stage W tile [D][128] -> bf16 hi/lo (once per CTA) ----
    for (int idx = tid; idx < D * 32; idx += 256) {
        int k  = idx >> 5;
        int c4 = (idx & 31) << 2;
        float4 v = *(const float4*)(W + k * HDIM + colbase + c4);
        uint32_t h0, h1, l0, l1; split4(v, h0, h1, l0, l1);
        *(uint2*)(smem + OFF_WHI + k * PW + c4 * 2)       = make_uint2(h0, h1);
        *(uint2*)(smem + OFF_WHI + WSZ + k * PW + c4 * 2) = make_uint2(l0, l1);
    }
    // first __syncthreads() inside the tile loop covers W visibility

    const int g   = lane >> 2;
    const int tig = lane & 3;
    // ldmatrix base addresses (row part from lane&15, 8-col hop from lane>>4)
    const uint32_t a_base = sb + OFF_AHI
        + (uint32_t)(wrow * 32 + (lane & 15)) * PA + ((lane >> 4) << 4);
    const uint32_t b_base = sb + OFF_WHI
        + (uint32_t)(lane & 15) * PW + ((wcol * 64 + ((lane >> 4) << 3)) << 1);

    for (int mt = blockIdx.y; mt < (B_NODES * KNEIGH) / 128; mt += gridDim.y) {
        float acc[2][8][4];
#pragma unroll
        for (int i = 0; i < 2; i++)
#pragma unroll
            for (int j = 0; j < 8; j++)
#pragma unroll
                for (int r = 0; r < 4; r++) acc[i][j][r] = 0.0f;

#pragma unroll
        for (int c0 = 0; c0 < D; c0 += KC) {
            __syncthreads();
            // ---- stage A chunk [128 rows][64 k] -> bf16 hi/lo ----
#pragma unroll
            for (int it = 0; it < 8; it++) {
                int idx = tid + it * 256;
                int r   = idx >> 4;
                int c4  = (idx & 15) << 2;
                float4 v = *(const float4*)(X + ((size_t)mt * 128 + r) * D + c0 + c4);
                uint32_t h0, h1, l0, l1; split4(v, h0, h1, l0, l1);
                *(uint2*)(smem + OFF_AHI + r * PA + c4 * 2)       = make_uint2(h0, h1);
                *(uint2*)(smem + OFF_ALO + r * PA + c4 * 2)       = make_uint2(l0, l1);
            }
            __syncthreads();

#pragma unroll
            for (int ks = 0; ks < KC / 16; ks++) {
                uint32_t ah[2][4], al[2][4];
#pragma unroll
                for (int mtile = 0; mtile < 2; mtile++) {
                    uint32_t aa = a_base + mtile * 16 * PA + ks * 32;  // ks*16 elems * 2B
                    ldsm_x4(ah[mtile], aa);
                    ldsm_x4(al[mtile], aa + ASZ);
                }
#pragma unroll
                for (int nb = 0; nb < 4; nb++) {
                    uint32_t ba = b_base + (uint32_t)(c0 + ks * 16) * PW + nb * 32;
                    uint32_t bh[4], bl[4];
                    ldsm_x4_t(bh, ba);
                    ldsm_x4_t(bl, ba + WSZ);
#pragma unroll
                    for (int mtile = 0; mtile < 2; mtile++) {
                        mma16816(acc[mtile][2 * nb],     ah[mtile], bh[0], bh[1]);
                        mma16816(acc[mtile][2 * nb],     ah[mtile], bl[0], bl[1]);
                        mma16816(acc[mtile][2 * nb],     al[mtile], bh[0], bh[1]);
                        mma16816(acc[mtile][2 * nb + 1], ah[mtile], bh[2], bh[3]);
                        mma16816(acc[mtile][2 * nb + 1], ah[mtile], bl[2], bl[3]);
                        mma16816(acc[mtile][2 * nb + 1], al[mtile], bh[2], bh[3]);
                    }
                }
            }
        }

        // ---- epilogue: bias + relu, pool the warp's 32 rows ----
        // D frag layout: d0:(row g, col 2tig) d1:(g,2tig+1) d2:(g+8,2tig) d3:(g+8,2tig+1)
        const int b = mt * 4 + wrow;
#pragma unroll
        for (int nt = 0; nt < 8; nt++) {
            int col = wcol * 64 + nt * 8 + tig * 2;
            float bv0 = bias_s[col], bv1 = bias_s[col + 1];
            float s0 = fmaxf(acc[0][nt][0] + bv0, 0.f) + fmaxf(acc[0][nt][2] + bv0, 0.f)
                     + fmaxf(acc[1][nt][0] + bv0, 0.f) + fmaxf(acc[1][nt][2] + bv0, 0.f);
            float s1 = fmaxf(acc[0][nt][1] + bv1, 0.f) + fmaxf(acc[0][nt][3] + bv1, 0.f)
                     + fmaxf(acc[1][nt][1] + bv1, 0.f) + fmaxf(acc[1][nt][3] + bv1, 0.f);
#pragma unroll
            for (int s = 4; s <= 16; s <<= 1) {
                s0 += __shfl_xor_sync(0xffffffffu, s0, s);
                s1 += __shfl_xor_sync(0xffffffffu, s1, s);
            }
            if (g == 0) {
                float2 o = make_float2(s0 * (1.0f / 32.0f), s1 * (1.0f / 32.0f));
                *(float2*)&pooled[(size_t)b * HDIM + colbase + col] = o;
            }
        }
    }
}

// =====================================================================
// Kernel 2 (SIMT, unchanged from passing R4): out = relu(self@Wself +
// pooled@Wneigh). 128x128 tile, f32x2 accumulators.
// =====================================================================
template <int DSELF, int WHICH>
__global__ void __launch_bounds__(256, 2)
combine_kernel(const float* __restrict__ Aself,
               const float* __restrict__ Wself,
               const float* __restrict__ Wneigh,
               float* __restrict__ out)
{
    __shared__ float As[128][33];
    __shared__ __align__(16) float Ws[32][128];

    const int tid = threadIdx.x;
    const int tx  = tid & 15;
    const int ty  = tid >> 4;
    const int colbase = blockIdx.x * 128;
    const int rowbase = blockIdx.y * 128;
    const float* pooled = WHICH ? g_geto_pooled : g_feat_pooled;

    unsigned long long acc[8][4];
#pragma unroll
    for (int i = 0; i < 8; i++)
#pragma unroll
        for (int p = 0; p < 4; p++) acc[i][p] = 0ull;

    const int NC1 = DSELF / 32;
    for (int ch = 0; ch < NC1 + HDIM / 32; ch++) {
        const float* A;
        const float* Wp;
        int lda, c0;
        if (ch < NC1) { A = Aself;  Wp = Wself;  lda = DSELF; c0 = ch * 32; }
        else          { A = pooled; Wp = Wneigh; lda = HDIM;  c0 = (ch - NC1) * 32; }

        __syncthreads();
#pragma unroll
        for (int it = 0; it < 4; it++) {
            int idx = tid + it * 256;
            int row = idx >> 3;
            int j   = (idx & 7) * 4;
            float4 v = *(const float4*)(A + (rowbase + row) * lda + c0 + j);
            As[row][j]     = v.x;
            As[row][j + 1] = v.y;
            As[row][j + 2] = v.z;
            As[row][j + 3] = v.w;
        }
#pragma unroll
        for (int it = 0; it < 4; it++) {
            int idx = tid + it * 256;
            int d = idx >> 5;
            int j = (idx & 31) * 4;
            *(float4*)&Ws[d][j] = *(const float4*)(Wp + (c0 + d) * DOUT + colbase + j);
        }
        __syncthreads();

#pragma unroll 8
        for (int dj = 0; dj < 32; dj++) {
            unsigned long long a2[8];
#pragma unroll
            for (int i = 0; i < 8; i++) {
                float a = As[ty * 8 + i][dj];
                a2[i] = pack2(a, a);
            }
            longlong2 w01 = *(const longlong2*)&Ws[dj][tx * 8];
            longlong2 w23 = *(const longlong2*)&Ws[dj][tx * 8 + 4];
            unsigned long long b0 = (unsigned long long)w01.x;
            unsigned long long b1 = (unsigned long long)w01.y;
            unsigned long long b2 = (unsigned long long)w23.x;
            unsigned long long b3 = (unsigned long long)w23.y;
#pragma unroll
            for (int i = 0; i < 8; i++) {
                fma2(acc[i][0], a2[i], b0);
                fma2(acc[i][1], a2[i], b1);
                fma2(acc[i][2], a2[i], b2);
                fma2(acc[i][3], a2[i], b3);
            }
        }
    }

#pragma unroll
    for (int i = 0; i < 8; i++) {
        int row = rowbase + ty * 8 + i;
#pragma unroll
        for (int p = 0; p < 4; p++) {
            float2 v = unpack2(acc[i][p]);
            v.x = fmaxf(v.x, 0.0f);
            v.y = fmaxf(v.y, 0.0f);
            *(float2*)(out + row * DOUT + colbase + tx * 8 + 2 * p) = v;
        }
    }
}

// =====================================================================
// Launch. Input order per metadata:
//  0 self_vecs[B,128] 1 neigh_vecs[B,K,128] 2 self_geto[B,64] 3 neigh_geto[B,K,64]
//  4 W_feat_mlp[128,512] 5 b_feat_mlp[512] 6 W_geto_mlp[64,512] 7 b_geto_mlp[512]
//  8 neigh_feat_weights[512,256] 9 self_feat_weights[128,256]
// 10 self_geto_weights[64,256]  11 neigh_geto_weights[512,256]
// =====================================================================
extern "C" void kernel_launch(void* const* d_in, const int* in_sizes, int n_in,
                              void* d_out, int out_size)
{
    const float* self_vecs  = (const float*)d_in[0];
    const float* neigh_vecs = (const float*)d_in[1];
    const float* self_geto  = (const float*)d_in[2];
    const float* neigh_geto = (const float*)d_in[3];
    const float* W_feat     = (const float*)d_in[4];
    const float* b_feat     = (const float*)d_in[5];
    const float* W_geto     = (const float*)d_in[6];
    const float* b_geto     = (const float*)d_in[7];
    const float* W_nf       = (const float*)d_in[8];
    const float* W_sf       = (const float*)d_in[9];
    const float* W_sg       = (const float*)d_in[10];
    const float* W_ng       = (const float*)d_in[11];
    float* out = (float*)d_out;

    // smem: 512 (bias) + 2 * 128*144 (A hi/lo) + 2 * D*272 (W hi/lo)
    const int smf = 512 + 2 * 128 * 144 + 2 * 128 * 272;   // 107008
    const int smg = 512 + 2 * 128 * 144 + 2 *  64 * 272;   //  72192
    static bool attr_done = false;
    if (!attr_done) {
        cudaFuncSetAttribute(pool_mma_kernel<128, 0>,
                             cudaFuncAttributeMaxDynamicSharedMemorySize, smf);
        cudaFuncSetAttribute(pool_mma_kernel<64, 1>,
                             cudaFuncAttributeMaxDynamicSharedMemorySize, smg);
        attr_done = true;
    }

    dim3 gp(4, 512);   // 4 col-tiles x grid-stride over 4096 row-tiles
    pool_mma_kernel<128, 0><<<gp, 256, smf>>>(neigh_vecs, W_feat, b_feat);
    pool_mma_kernel<64, 1><<<gp, 256, smg>>>(neigh_geto, W_geto, b_geto);

    dim3 blk(256);
    dim3 grid_comb(DOUT / 128, B_NODES / 128);
    combine_kernel<128, 0><<<grid_comb, blk>>>(self_vecs, W_sf, W_nf, out);
    combine_kernel<64, 1><<<grid_comb, blk>>>(self_geto, W_sg, W_ng,
                                              out + B_NODES * DOUT);
}

// round 7
// speedup vs baseline: 2.6728x; 1.1737x over previous
#include <cuda_runtime.h>
#include <cuda_bf16.h>
#include <cstdint>

// Problem constants (fixed by the reference setup_inputs)
#define B_NODES 16384
#define KNEIGH  32
#define HDIM    512
#define DOUT    256

// Pooled hidden activations (scratch): 2 x 16384 x 512 f32 = 64 MB static device mem
__device__ float g_feat_pooled[B_NODES * HDIM];
__device__ float g_geto_pooled[B_NODES * HDIM];

// =====================================================================
// Helpers
// =====================================================================
__device__ __forceinline__ uint32_t smem_u32(const void* p) {
    uint32_t a;
    asm("{ .reg .u64 t; cvta.to.shared.u64 t, %1; cvt.u32.u64 %0, t; }"
        : "=r"(a) : "l"(p));
    return a;
}

__device__ __forceinline__ void ldsm_x4(uint32_t r[4], uint32_t addr) {
    asm volatile("ldmatrix.sync.aligned.m8n8.x4.shared.b16 {%0,%1,%2,%3}, [%4];"
        : "=r"(r[0]), "=r"(r[1]), "=r"(r[2]), "=r"(r[3]) : "r"(addr));
}
__device__ __forceinline__ void ldsm_x4_t(uint32_t r[4], uint32_t addr) {
    asm volatile("ldmatrix.sync.aligned.m8n8.x4.trans.shared.b16 {%0,%1,%2,%3}, [%4];"
        : "=r"(r[0]), "=r"(r[1]), "=r"(r[2]), "=r"(r[3]) : "r"(addr));
}
__device__ __forceinline__ void mma16816(float c[4], const uint32_t a[4],
                                         uint32_t b0, uint32_t b1) {
    asm volatile("mma.sync.aligned.m16n8k16.row.col.f32.bf16.bf16.f32 "
        "{%0,%1,%2,%3}, {%4,%5,%6,%7}, {%8,%9}, {%0,%1,%2,%3};"
        : "+f"(c[0]), "+f"(c[1]), "+f"(c[2]), "+f"(c[3])
        : "r"(a[0]), "r"(a[1]), "r"(a[2]), "r"(a[3]), "r"(b0), "r"(b1));
}

// split fp32x4 -> bf16 hi pair + lo (residual) pair
__device__ __forceinline__ void split4(float4 v, uint32_t& h0, uint32_t& h1,
                                       uint32_t& l0, uint32_t& l1) {
    __nv_bfloat16 hx = __float2bfloat16(v.x), hy = __float2bfloat16(v.y);
    __nv_bfloat16 hz = __float2bfloat16(v.z), hw = __float2bfloat16(v.w);
    __nv_bfloat162 H0; H0.x = hx; H0.y = hy;
    __nv_bfloat162 H1; H1.x = hz; H1.y = hw;
    h0 = *(uint32_t*)&H0; h1 = *(uint32_t*)&H1;
    __nv_bfloat162 L0, L1;
    L0.x = __float2bfloat16(v.x - __bfloat162float(hx));
    L0.y = __float2bfloat16(v.y - __bfloat162float(hy));
    L1.x = __float2bfloat16(v.z - __bfloat162float(hz));
    L1.y = __float2bfloat16(v.w - __bfloat162float(hw));
    l0 = *(uint32_t*)&L0; l1 = *(uint32_t*)&L1;
}

// =====================================================================
// Kernel 1 (mma.sync bf16 3-split): fused per-neighbor MLP + ReLU + mean-pool
//   X[B*K, D] fp32 ; W[D, 512] ; bias[512]
//   pooled[b][h] = mean_k relu(X[b*32+k,:] @ W[:,h] + bias[h])
// CTA: 256 thr / 8 warps; tile 128 rows x 128 cols.
// warp (wrow,wcol): 32 rows (one batch) x 64 cols.
// W tile staged hi/lo once per CTA; A staged per tile in k=64 chunks.
// =====================================================================
template <int D, int WHICH>
__global__ void __launch_bounds__(256, 2)
pool_mma_kernel(const float* __restrict__ X,
                const float* __restrict__ W,
                const float* __restrict__ bias)
{
    constexpr int KC  = 64;                // k-chunk size
    constexpr int PA  = 144;               // A pitch bytes (64 bf16 + 16B pad)
    constexpr int PW  = 272;               // W pitch bytes (128 bf16 + 16B pad)
    constexpr int ASZ = 128 * PA;          // per-split A tile bytes
    constexpr int WSZ = D * PW;            // per-split W tile bytes
    constexpr int OFF_AHI = 512;
    constexpr int OFF_ALO = OFF_AHI + ASZ;
    constexpr int OFF_WHI = OFF_ALO + ASZ;

    extern __shared__ char smem[];
    float* bias_s = (float*)smem;
    const uint32_t sb = smem_u32(smem);
    const int tid  = threadIdx.x;
    const int lane = tid & 31;
    const int wid  = tid >> 5;
    const int wrow = wid & 3;              // 32-row group (batch within tile)
    const int wcol = wid >> 2;             // 64-col half
    const int colbase = blockIdx.x * 128;
    float* pooled = WHICH ? g_geto_pooled : g_feat_pooled;

    if (tid < 128) bias_s[tid] = bias[colbase + tid];

    // ---- stage W tile [D][128] -> bf16 hi/lo (once per CTA) ----
    for (int idx = tid; idx < D * 32; idx += 256) {
        int k  = idx >> 5;
        int c4 = (idx & 31) << 2;
        float4 v = *(const float4*)(W + k * HDIM + colbase + c4);
        uint32_t h0, h1, l0, l1; split4(v, h0, h1, l0, l1);
        *(uint2*)(smem + OFF_WHI + k * PW + c4 * 2)       = make_uint2(h0, h1);
        *(uint2*)(smem + OFF_WHI + WSZ + k * PW + c4 * 2) = make_uint2(l0, l1);
    }
    // first __syncthreads() inside the tile loop covers W visibility

    const int g   = lane >> 2;
    const int tig = lane & 3;
    // ldmatrix base addresses (row part from lane&15, 8-col hop from lane>>4)
    const uint32_t a_base = sb + OFF_AHI
        + (uint32_t)(wrow * 32 + (lane & 15)) * PA + ((lane >> 4) << 4);
    const uint32_t b_base = sb + OFF_WHI
        + (uint32_t)(lane & 15) * PW + ((wcol * 64 + ((lane >> 4) << 3)) << 1);

    for (int mt = blockIdx.y; mt < (B_NODES * KNEIGH) / 128; mt += gridDim.y) {
        float acc[2][8][4];
#pragma unroll
        for (int i = 0; i < 2; i++)
#pragma unroll
            for (int j = 0; j < 8; j++)
#pragma unroll
                for (int r = 0; r < 4; r++) acc[i][j][r] = 0.0f;

#pragma unroll
        for (int c0 = 0; c0 < D; c0 += KC) {
            __syncthreads();
            // ---- stage A chunk [128 rows][64 k] -> bf16 hi/lo ----
#pragma unroll
            for (int it = 0; it < 8; it++) {
                int idx = tid + it * 256;
                int r   = idx >> 4;
                int c4  = (idx & 15) << 2;
                float4 v = *(const float4*)(X + ((size_t)mt * 128 + r) * D + c0 + c4);
                uint32_t h0, h1, l0, l1; split4(v, h0, h1, l0, l1);
                *(uint2*)(smem + OFF_AHI + r * PA + c4 * 2)       = make_uint2(h0, h1);
                *(uint2*)(smem + OFF_ALO + r * PA + c4 * 2)       = make_uint2(l0, l1);
            }
            __syncthreads();

#pragma unroll
            for (int ks = 0; ks < KC / 16; ks++) {
                uint32_t ah[2][4], al[2][4];
#pragma unroll
                for (int mtile = 0; mtile < 2; mtile++) {
                    uint32_t aa = a_base + mtile * 16 * PA + ks * 32;  // ks*16 elems * 2B
                    ldsm_x4(ah[mtile], aa);
                    ldsm_x4(al[mtile], aa + ASZ);
                }
#pragma unroll
                for (int nb = 0; nb < 4; nb++) {
                    uint32_t ba = b_base + (uint32_t)(c0 + ks * 16) * PW + nb * 32;
                    uint32_t bh[4], bl[4];
                    ldsm_x4_t(bh, ba);
                    ldsm_x4_t(bl, ba + WSZ);
#pragma unroll
                    for (int mtile = 0; mtile < 2; mtile++) {
                        mma16816(acc[mtile][2 * nb],     ah[mtile], bh[0], bh[1]);
                        mma16816(acc[mtile][2 * nb],     ah[mtile], bl[0], bl[1]);
                        mma16816(acc[mtile][2 * nb],     al[mtile], bh[0], bh[1]);
                        mma16816(acc[mtile][2 * nb + 1], ah[mtile], bh[2], bh[3]);
                        mma16816(acc[mtile][2 * nb + 1], ah[mtile], bl[2], bl[3]);
                        mma16816(acc[mtile][2 * nb + 1], al[mtile], bh[2], bh[3]);
                    }
                }
            }
        }

        // ---- epilogue: bias + relu, pool the warp's 32 rows ----
        // D frag layout: d0:(row g, col 2tig) d1:(g,2tig+1) d2:(g+8,2tig) d3:(g+8,2tig+1)
        const int b = mt * 4 + wrow;
#pragma unroll
        for (int nt = 0; nt < 8; nt++) {
            int col = wcol * 64 + nt * 8 + tig * 2;
            float bv0 = bias_s[col], bv1 = bias_s[col + 1];
            float s0 = fmaxf(acc[0][nt][0] + bv0, 0.f) + fmaxf(acc[0][nt][2] + bv0, 0.f)
                     + fmaxf(acc[1][nt][0] + bv0, 0.f) + fmaxf(acc[1][nt][2] + bv0, 0.f);
            float s1 = fmaxf(acc[0][nt][1] + bv1, 0.f) + fmaxf(acc[0][nt][3] + bv1, 0.f)
                     + fmaxf(acc[1][nt][1] + bv1, 0.f) + fmaxf(acc[1][nt][3] + bv1, 0.f);
#pragma unroll
            for (int s = 4; s <= 16; s <<= 1) {
                s0 += __shfl_xor_sync(0xffffffffu, s0, s);
                s1 += __shfl_xor_sync(0xffffffffu, s1, s);
            }
            if (g == 0) {
                float2 o = make_float2(s0 * (1.0f / 32.0f), s1 * (1.0f / 32.0f));
                *(float2*)&pooled[(size_t)b * HDIM + colbase + col] = o;
            }
        }
    }
}

// =====================================================================
// Kernel 2 (mma.sync bf16 3-split): out = relu(self@Wself + pooled@Wneigh)
// Virtual-depth GEMM over [self | pooled] (depth DSELF + 512), chunked
// by 64; both A and W chunks split hi/lo in SMEM per chunk.
// CTA: 256 thr / 8 warps; tile 128 rows x 128 cols; grid (2, 128).
// =====================================================================
template <int DSELF, int WHICH>
__global__ void __launch_bounds__(256, 2)
combine_mma_kernel(const float* __restrict__ Aself,
                   const float* __restrict__ Wself,
                   const float* __restrict__ Wneigh,
                   float* __restrict__ out)
{
    constexpr int KC  = 64;
    constexpr int PA  = 144;               // A pitch bytes
    constexpr int PW  = 272;               // W pitch bytes
    constexpr int ASZ = 128 * PA;
    constexpr int WSZ = KC * PW;
    constexpr int OFF_AHI = 0;
    constexpr int OFF_ALO = OFF_AHI + ASZ;
    constexpr int OFF_WHI = OFF_ALO + ASZ;
    constexpr int NSELF = DSELF / KC;      // self chunks (2 or 1)
    constexpr int NCH   = NSELF + HDIM / KC;

    extern __shared__ char smem[];
    const uint32_t sb = smem_u32(smem);
    const int tid  = threadIdx.x;
    const int lane = tid & 31;
    const int wid  = tid >> 5;
    const int wrow = wid & 3;
    const int wcol = wid >> 2;
    const int colbase = blockIdx.x * 128;
    const int rowbase = blockIdx.y * 128;
    const float* pooled = WHICH ? g_geto_pooled : g_feat_pooled;

    const int g   = lane >> 2;
    const int tig = lane & 3;
    const uint32_t a_base = sb + OFF_AHI
        + (uint32_t)(wrow * 32 + (lane & 15)) * PA + ((lane >> 4) << 4);
    const uint32_t b_base = sb + OFF_WHI
        + (uint32_t)(lane & 15) * PW + ((wcol * 64 + ((lane >> 4) << 3)) << 1);

    float acc[2][8][4];
#pragma unroll
    for (int i = 0; i < 2; i++)
#pragma unroll
        for (int j = 0; j < 8; j++)
#pragma unroll
            for (int r = 0; r < 4; r++) acc[i][j][r] = 0.0f;

#pragma unroll
    for (int ch = 0; ch < NCH; ch++) {
        const float* A;
        const float* Wp;
        int lda, c0;
        if (ch < NSELF) { A = Aself;  Wp = Wself;  lda = DSELF; c0 = ch * KC; }
        else            { A = pooled; Wp = Wneigh; lda = HDIM;  c0 = (ch - NSELF) * KC; }

        __syncthreads();
        // ---- stage A chunk [128 rows][64 k] hi/lo ----
#pragma unroll
        for (int it = 0; it < 8; it++) {
            int idx = tid + it * 256;
            int r   = idx >> 4;
            int c4  = (idx & 15) << 2;
            float4 v = *(const float4*)(A + ((size_t)(rowbase + r)) * lda + c0 + c4);
            uint32_t h0, h1, l0, l1; split4(v, h0, h1, l0, l1);
            *(uint2*)(smem + OFF_AHI + r * PA + c4 * 2) = make_uint2(h0, h1);
            *(uint2*)(smem + OFF_ALO + r * PA + c4 * 2) = make_uint2(l0, l1);
        }
        // ---- stage W chunk [64 depth][128 cols] hi/lo ----
#pragma unroll
        for (int it = 0; it < 8; it++) {
            int idx = tid + it * 256;
            int k  = idx >> 5;              // 0..63
            int c4 = (idx & 31) << 2;       // 0..124
            float4 v = *(const float4*)(Wp + (size_t)(c0 + k) * DOUT + colbase + c4);
            uint32_t h0, h1, l0, l1; split4(v, h0, h1, l0, l1);
            *(uint2*)(smem + OFF_WHI + k * PW + c4 * 2)       = make_uint2(h0, h1);
            *(uint2*)(smem + OFF_WHI + WSZ + k * PW + c4 * 2) = make_uint2(l0, l1);
        }
        __syncthreads();

#pragma unroll
        for (int ks = 0; ks < KC / 16; ks++) {
            uint32_t ah[2][4], al[2][4];
#pragma unroll
            for (int mtile = 0; mtile < 2; mtile++) {
                uint32_t aa = a_base + mtile * 16 * PA + ks * 32;
                ldsm_x4(ah[mtile], aa);
                ldsm_x4(al[mtile], aa + ASZ);
            }
#pragma unroll
            for (int nb = 0; nb < 4; nb++) {
                uint32_t ba = b_base + (uint32_t)(ks * 16) * PW + nb * 32;
                uint32_t bh[4], bl[4];
                ldsm_x4_t(bh, ba);
                ldsm_x4_t(bl, ba + WSZ);
#pragma unroll
                for (int mtile = 0; mtile < 2; mtile++) {
                    mma16816(acc[mtile][2 * nb],     ah[mtile], bh[0], bh[1]);
                    mma16816(acc[mtile][2 * nb],     ah[mtile], bl[0], bl[1]);
                    mma16816(acc[mtile][2 * nb],     al[mtile], bh[0], bh[1]);
                    mma16816(acc[mtile][2 * nb + 1], ah[mtile], bh[2], bh[3]);
                    mma16816(acc[mtile][2 * nb + 1], ah[mtile], bl[2], bl[3]);
                    mma16816(acc[mtile][2 * nb + 1], al[mtile], bh[2], bh[3]);
                }
            }
        }
    }

    // ---- epilogue: relu + store fragments ----
#pragma unroll
    for (int mtile = 0; mtile < 2; mtile++) {
        int row0 = rowbase + wrow * 32 + mtile * 16 + g;
#pragma unroll
        for (int nt = 0; nt < 8; nt++) {
            int col = colbase + wcol * 64 + nt * 8 + tig * 2;
            float2 v0 = make_float2(fmaxf(acc[mtile][nt][0], 0.f),
                                    fmaxf(acc[mtile][nt][1], 0.f));
            float2 v1 = make_float2(fmaxf(acc[mtile][nt][2], 0.f),
                                    fmaxf(acc[mtile][nt][3], 0.f));
            *(float2*)&out[(size_t)row0 * DOUT + col]       = v0;
            *(float2*)&out[(size_t)(row0 + 8) * DOUT + col] = v1;
        }
    }
}

// =====================================================================
// Launch. Input order per metadata:
//  0 self_vecs[B,128] 1 neigh_vecs[B,K,128] 2 self_geto[B,64] 3 neigh_geto[B,K,64]
//  4 W_feat_mlp[128,512] 5 b_feat_mlp[512] 6 W_geto_mlp[64,512] 7 b_geto_mlp[512]
//  8 neigh_feat_weights[512,256] 9 self_feat_weights[128,256]
// 10 self_geto_weights[64,256]  11 neigh_geto_weights[512,256]
// =====================================================================
extern "C" void kernel_launch(void* const* d_in, const int* in_sizes, int n_in,
                              void* d_out, int out_size)
{
    const float* self_vecs  = (const float*)d_in[0];
    const float* neigh_vecs = (const float*)d_in[1];
    const float* self_geto  = (const float*)d_in[2];
    const float* neigh_geto = (const float*)d_in[3];
    const float* W_feat     = (const float*)d_in[4];
    const float* b_feat     = (const float*)d_in[5];
    const float* W_geto     = (const float*)d_in[6];
    const float* b_geto     = (const float*)d_in[7];
    const float* W_nf       = (const float*)d_in[8];
    const float* W_sf       = (const float*)d_in[9];
    const float* W_sg       = (const float*)d_in[10];
    const float* W_ng       = (const float*)d_in[11];
    float* out = (float*)d_out;

    // pool smem: 512 (bias) + 2*128*144 (A hi/lo) + 2*D*272 (W hi/lo)
    const int smf = 512 + 2 * 128 * 144 + 2 * 128 * 272;   // 107008
    const int smg = 512 + 2 * 128 * 144 + 2 *  64 * 272;   //  72192
    // combine smem: 2*128*144 (A) + 2*64*272 (W chunk)
    const int smc = 2 * 128 * 144 + 2 * 64 * 272;          //  71680
    cudaFuncSetAttribute(pool_mma_kernel<128, 0>,
                         cudaFuncAttributeMaxDynamicSharedMemorySize, smf);
    cudaFuncSetAttribute(pool_mma_kernel<64, 1>,
                         cudaFuncAttributeMaxDynamicSharedMemorySize, smg);
    cudaFuncSetAttribute(combine_mma_kernel<128, 0>,
                         cudaFuncAttributeMaxDynamicSharedMemorySize, smc);
    cudaFuncSetAttribute(combine_mma_kernel<64, 1>,
                         cudaFuncAttributeMaxDynamicSharedMemorySize, smc);

    dim3 gp(4, 512);   // 4 col-tiles x grid-stride over 4096 row-tiles
    pool_mma_kernel<128, 0><<<gp, 256, smf>>>(neigh_vecs, W_feat, b_feat);
    pool_mma_kernel<64, 1><<<gp, 256, smg>>>(neigh_geto, W_geto, b_geto);

    dim3 gc(2, 128);   // 2 col-tiles x 128 row-tiles
    combine_mma_kernel<128, 0><<<gc, 256, smc>>>(self_vecs, W_sf, W_nf, out);
    combine_mma_kernel<64, 1><<<gc, 256, smc>>>(self_geto, W_sg, W_ng,
                                                out + B_NODES * DOUT);
}